// round 1
// baseline (speedup 1.0000x reference)
#include <cuda_runtime.h>
#include <cstdint>
#include <cstddef>

#define BATCHN 10
#define HID    128
#define OUTD   7
#define TLEN   2048
#define NCTA   8
#define KPC    16      // HID / NCTA hidden units owned per CTA
#define TPB    320     // 64 gate-rows * 5 batch-pairs

__device__ __forceinline__ uint32_t sm2u(const void* p) {
    return (uint32_t)__cvta_generic_to_shared(const_cast<void*>(p));
}
__device__ __forceinline__ uint32_t ctarank() {
    uint32_t r; asm("mov.u32 %0, %%cluster_ctarank;" : "=r"(r)); return r;
}
// store 4 bytes into the SMEM of cluster CTA `rk` at the same offset as local addr
__device__ __forceinline__ void dst_f32(uint32_t saddr, uint32_t rk, float v) {
    uint32_t ra;
    asm volatile("mapa.shared::cluster.u32 %0, %1, %2;" : "=r"(ra) : "r"(saddr), "r"(rk));
    asm volatile("st.shared::cluster.f32 [%0], %1;" :: "r"(ra), "f"(v) : "memory");
}
__device__ __forceinline__ void cluster_sync_all() {
    asm volatile("barrier.cluster.arrive.aligned;" ::: "memory");
    asm volatile("barrier.cluster.wait.aligned;"   ::: "memory");
}

__global__ void __cluster_dims__(NCTA, 1, 1) __launch_bounds__(TPB, 1)
lstm_decoder_kernel(const float* __restrict__ h0,
                    const float* __restrict__ c0,
                    const float* __restrict__ tonehot,   // (TLEN+1, 1, OUTD)
                    const void*  __restrict__ tfraw,     // tf_mask, dtype unknown (bool/int32/float)
                    const float* __restrict__ W_ih,      // (4*HID, OUTD)
                    const float* __restrict__ W_hh,      // (4*HID, HID)
                    const float* __restrict__ b_ih,
                    const float* __restrict__ b_hh,
                    const float* __restrict__ W_out,     // (OUTD, HID)
                    const float* __restrict__ b_out,
                    float* __restrict__ out)             // [143360 lp | 1280 hT | 1280 cT]
{
    __shared__ __align__(16) float h_s[2][BATCHN][HID];    // double-buffered full hidden state
    __shared__ float gates_s[BATCHN * 64];                 // activated gates, CTA's k-slice
    __shared__ float plog_s[2][NCTA][BATCHN * OUTD];       // partial logits from each CTA
    __shared__ float wih_s[4 * HID * OUTD];
    __shared__ float logits_s[BATCHN * OUTD];
    __shared__ int   xidx_s[BATCHN];
    __shared__ int   tgt_s[TLEN];
    __shared__ unsigned char tf_s[TLEN];
    __shared__ float bout_s[OUTD];
    __shared__ int   tfmode_s;

    const int tid  = threadIdx.x;
    const uint32_t rank = ctarank();

    // gate-dot decomposition: thread owns gate row g for 2 batches
    const int bp   = tid / 64;        // batch pair 0..4
    const int r    = tid % 64;        // local gate row (type*16 + klocal)
    const int type = r >> 4;          // 0=i 1=f 2=g 3=o
    const int kl   = r & 15;
    const int g    = type * HID + (int)rank * KPC + kl;

    // W_hh row g lives in registers (128 floats)
    float w[HID];
#pragma unroll
    for (int i = 0; i < HID / 4; i++) {
        float4 v = reinterpret_cast<const float4*>(W_hh + (size_t)g * HID)[i];
        w[4*i] = v.x; w[4*i+1] = v.y; w[4*i+2] = v.z; w[4*i+3] = v.w;
    }
    const float biasg = b_ih[g] + b_hh[g];

    // pointwise role: first 160 threads own one (batch, hidden-unit) each
    const bool is_pw = tid < BATCHN * KPC;
    const int  pb = tid >> 4;
    const int  pk = tid & 15;
    const int  kg = (int)rank * KPC + pk;     // global hidden index
    float cval = 0.f;
    float wout[OUTD];
    if (is_pw) {
        cval = c0[pb * HID + kg];
#pragma unroll
        for (int o = 0; o < OUTD; o++) wout[o] = W_out[o * HID + kg];
    }

    // ---- init shared state ----
    for (int i = tid; i < BATCHN * HID; i += TPB) ((float*)h_s[0])[i] = h0[i];
    for (int i = tid; i < 4 * HID * OUTD; i += TPB) wih_s[i] = W_ih[i];
    if (tid < OUTD)   bout_s[tid] = b_out[tid];
    if (tid < BATCHN) xidx_s[tid] = OUTD - 1;     // x0 is one-hot at column OUT-1

    // tf_mask dtype autodetect (bool bytes vs int32 vs float32). First 512 ints
    // = 2048 bytes, safe in all encodings.
    if (tid == 0) {
        const int* ip = (const int*)tfraw;
        int mode = 0;                               // default: int32 {0,1}
        for (int i = 0; i < 512; i++) {
            int v = ip[i];
            if (v == 0x3f800000) { mode = 1; break; }   // float32 1.0f seen
            if (v != 0 && v != 1) mode = 2;             // packed bool bytes
        }
        tfmode_s = mode;
    }
    __syncthreads();
    {
        const int mode = tfmode_s;
        for (int s = tid; s < TLEN; s += TPB) {
            unsigned char tv;
            if (mode == 0)      tv = ((const int*)tfraw)[s] != 0;
            else if (mode == 1) tv = ((const float*)tfraw)[s] != 0.f;
            else                tv = ((const unsigned char*)tfraw)[s] != 0;
            tf_s[s] = tv;
            // tgt_next[s] = argmax(target_onehot[s+1]) — it is exactly one-hot
            const float* row = tonehot + (size_t)(s + 1) * OUTD;
            int idx = 0; float best = row[0];
#pragma unroll
            for (int o = 1; o < OUTD; o++) { if (row[o] > best) { best = row[o]; idx = o; } }
            tgt_s[s] = idx;
        }
    }
    __syncthreads();

    // ================= main sequential loop =================
    for (int t = 0; t < TLEN; t++) {
        const int p = t & 1;

        // ---- stage 1: recurrent dots (no dependence on x index) ----
        float aA0=0,aA1=0,aA2=0,aA3=0, aB0=0,aB1=0,aB2=0,aB3=0;
        const float4* hA = reinterpret_cast<const float4*>(h_s[p][bp*2]);
        const float4* hB = reinterpret_cast<const float4*>(h_s[p][bp*2 + 1]);
#pragma unroll
        for (int i = 0; i < HID / 4; i++) {
            float4 va = hA[i]; float4 vb = hB[i];
            aA0 += w[4*i  ] * va.x; aA1 += w[4*i+1] * va.y;
            aA2 += w[4*i+2] * va.z; aA3 += w[4*i+3] * va.w;
            aB0 += w[4*i  ] * vb.x; aB1 += w[4*i+1] * vb.y;
            aB2 += w[4*i+2] * vb.z; aB3 += w[4*i+3] * vb.w;
        }
        const float dotA = (aA0 + aA1) + (aA2 + aA3);
        const float dotB = (aB0 + aB1) + (aB2 + aB3);

        // ---- stage 2: finish logits(t-1) -> output, argmax, next x index ----
        if (t > 0) {
            if (tid < BATCHN * OUTD) {
                float s = bout_s[tid % OUTD];
#pragma unroll
                for (int rr = 0; rr < NCTA; rr++) s += plog_s[p][rr][tid];
                logits_s[tid] = s;
            }
            __syncthreads();
            if (tid < BATCHN) {
                float l[OUTD];
#pragma unroll
                for (int o = 0; o < OUTD; o++) l[o] = logits_s[tid * OUTD + o];
                int am = 0; float best = l[0];
#pragma unroll
                for (int o = 1; o < OUTD; o++) if (l[o] > best) { best = l[o]; am = o; }
                float se = 0.f;
#pragma unroll
                for (int o = 0; o < OUTD; o++) se += expf(l[o] - best);
                const float lse = best + logf(se);
                if (rank == 0) {
                    float* op = out + (size_t)tid * TLEN * OUTD + (size_t)(t - 1) * OUTD;
#pragma unroll
                    for (int o = 0; o < OUTD; o++) op[o] = l[o] - lse;
                }
                xidx_s[tid] = tf_s[t - 1] ? tgt_s[t - 1] : am;
            }
        }
        __syncthreads();

        // ---- stage 3: add one-hot input column + bias, activate, share gates ----
        {
            float vA = dotA + biasg + wih_s[g * OUTD + xidx_s[bp*2]];
            float vB = dotB + biasg + wih_s[g * OUTD + xidx_s[bp*2 + 1]];
            if (type == 2) { vA = tanhf(vA); vB = tanhf(vB); }
            else { vA = 1.f / (1.f + expf(-vA)); vB = 1.f / (1.f + expf(-vB)); }
            gates_s[(bp*2    ) * 64 + r] = vA;
            gates_s[(bp*2 + 1) * 64 + r] = vB;
        }
        __syncthreads();

        // ---- stage 4: LSTM pointwise, broadcast h, partial output logits ----
        if (is_pw) {
            const float ig = gates_s[pb * 64 +      pk];
            const float fg = gates_s[pb * 64 + 16 + pk];
            const float gg = gates_s[pb * 64 + 32 + pk];
            const float og = gates_s[pb * 64 + 48 + pk];
            cval = fg * cval + ig * gg;
            const float h2 = og * tanhf(cval);

            // broadcast h2 into every CTA's next-parity h buffer
            const uint32_t hoff = sm2u(&h_s[p ^ 1][pb][kg]);
#pragma unroll
            for (uint32_t rr = 0; rr < NCTA; rr++) dst_f32(hoff, rr, h2);

            // partial logits for this CTA's k-slice, reduced over 16 lanes
            float pl[OUTD];
#pragma unroll
            for (int o = 0; o < OUTD; o++) pl[o] = h2 * wout[o];
#pragma unroll
            for (int d = 8; d >= 1; d >>= 1) {
#pragma unroll
                for (int o = 0; o < OUTD; o++)
                    pl[o] += __shfl_xor_sync(0xffffffffu, pl[o], d);
            }
            if (pk < OUTD) {
                float myv = pl[0];
#pragma unroll
                for (int o = 1; o < OUTD; o++) if (pk == o) myv = pl[o];
                const uint32_t poff = sm2u(&plog_s[p ^ 1][rank][pb * OUTD + pk]);
#pragma unroll
                for (uint32_t rr = 0; rr < NCTA; rr++) dst_f32(poff, rr, myv);
            }
        }
        cluster_sync_all();   // release h2/plog stores, fence next iteration
    }

    // ================= epilogue: logits for t = TLEN-1, final states =================
    {
        const int p = TLEN & 1;   // buffer written by last iteration
        if (tid < BATCHN * OUTD) {
            float s = bout_s[tid % OUTD];
#pragma unroll
            for (int rr = 0; rr < NCTA; rr++) s += plog_s[p][rr][tid];
            logits_s[tid] = s;
        }
        __syncthreads();
        if (rank == 0 && tid < BATCHN) {
            float l[OUTD];
#pragma unroll
            for (int o = 0; o < OUTD; o++) l[o] = logits_s[tid * OUTD + o];
            float best = l[0];
#pragma unroll
            for (int o = 1; o < OUTD; o++) if (l[o] > best) best = l[o];
            float se = 0.f;
#pragma unroll
            for (int o = 0; o < OUTD; o++) se += expf(l[o] - best);
            const float lse = best + logf(se);
            float* op = out + (size_t)tid * TLEN * OUTD + (size_t)(TLEN - 1) * OUTD;
#pragma unroll
            for (int o = 0; o < OUTD; o++) op[o] = l[o] - lse;
        }
        // hT (full h lives in every CTA's buffer parity TLEN&1)
        if (rank == 0) {
            for (int i = tid; i < BATCHN * HID; i += TPB)
                out[(size_t)BATCHN * TLEN * OUTD + i] = ((float*)h_s[TLEN & 1])[i];
        }
        // cT: each CTA writes the cell-state slice it owns (held in registers)
        if (is_pw)
            out[(size_t)BATCHN * TLEN * OUTD + BATCHN * HID + pb * HID + kg] = cval;
    }
}

extern "C" void kernel_launch(void* const* d_in, const int* in_sizes, int n_in,
                              void* d_out, int out_size) {
    (void)in_sizes; (void)n_in; (void)out_size;
    const float* h0    = (const float*)d_in[0];
    const float* c0    = (const float*)d_in[1];
    const float* toh   = (const float*)d_in[2];
    const void*  tf    = d_in[3];
    const float* W_ih  = (const float*)d_in[4];
    const float* W_hh  = (const float*)d_in[5];
    const float* b_ih  = (const float*)d_in[6];
    const float* b_hh  = (const float*)d_in[7];
    const float* W_out = (const float*)d_in[8];
    const float* b_out = (const float*)d_in[9];
    float* out = (float*)d_out;

    lstm_decoder_kernel<<<NCTA, TPB>>>(h0, c0, toh, tf, W_ih, W_hh,
                                       b_ih, b_hh, W_out, b_out, out);
}